// round 1
// baseline (speedup 1.0000x reference)
#include <cuda_runtime.h>

#define B_SZ 8192
#define D_SZ 256

// ---------------- device scratch (no allocations allowed) ----------------
__device__ float    g_An[B_SZ * D_SZ];   // normalized audio
__device__ float    g_Tn[B_SZ * D_SZ];   // normalized text
__device__ unsigned g_rowmax[B_SZ];      // encoded-float max over row (label-unequal)
__device__ unsigned g_colmax[B_SZ];      // encoded-float max over col (label-unequal)
__device__ float    g_diag[B_SZ];        // S[i,i]
__device__ float    g_partial[32];       // block partial sums (deterministic reduce)

// Order-preserving float<->uint encoding so atomicMax works for signed floats.
__device__ __forceinline__ unsigned fenc(float f) {
    unsigned u = __float_as_uint(f);
    return (u & 0x80000000u) ? ~u : (u | 0x80000000u);
}
__device__ __forceinline__ float fdec(unsigned u) {
    return (u & 0x80000000u) ? __uint_as_float(u ^ 0x80000000u)
                             : __uint_as_float(~u);
}

// ---------------- init ----------------
__global__ void init_kernel() {
    int i = blockIdx.x * 256 + threadIdx.x;
    if (i < B_SZ) {
        unsigned s = fenc(-1e9f);   // NEG_SENTINEL semantics
        g_rowmax[i] = s;
        g_colmax[i] = s;
    }
}

// ---------------- row L2-normalize both matrices (1 warp / row) ----------------
__global__ void normalize_kernel(const float* __restrict__ A,
                                 const float* __restrict__ T) {
    int row  = blockIdx.x * blockDim.y + threadIdx.y;   // 0 .. 2B-1
    int lane = threadIdx.x;
    const float* src;
    float* dst;
    if (row < B_SZ) { src = A + (size_t)row * D_SZ;            dst = g_An + (size_t)row * D_SZ; }
    else            { src = T + (size_t)(row - B_SZ) * D_SZ;   dst = g_Tn + (size_t)(row - B_SZ) * D_SZ; }

    float4 v0 = ((const float4*)src)[lane];
    float4 v1 = ((const float4*)src)[lane + 32];
    float ss = v0.x*v0.x + v0.y*v0.y + v0.z*v0.z + v0.w*v0.w
             + v1.x*v1.x + v1.y*v1.y + v1.z*v1.z + v1.w*v1.w;
    #pragma unroll
    for (int o = 16; o > 0; o >>= 1) ss += __shfl_xor_sync(0xffffffffu, ss, o);
    float inv = 1.0f / sqrtf(ss);
    v0.x *= inv; v0.y *= inv; v0.z *= inv; v0.w *= inv;
    v1.x *= inv; v1.y *= inv; v1.z *= inv; v1.w *= inv;
    ((float4*)dst)[lane]      = v0;
    ((float4*)dst)[lane + 32] = v1;
}

// ---------------- fused GEMM (S tile) + diag capture + row/col max ----------------
// BM = BN = 128, BK = 16, 256 threads, 8x8 microtile per thread.
__global__ void gemm_max_kernel(const long long* __restrict__ labels) {
    __shared__ float    As[16][128];
    __shared__ float    Bs[16][128];
    __shared__ unsigned smax_r[128];
    __shared__ unsigned smax_c[128];

    const int tid = threadIdx.x;
    const int bx = blockIdx.x, by = blockIdx.y;

    if (tid < 128) {
        unsigned s = fenc(-3e38f);
        smax_r[tid] = s;
        smax_c[tid] = s;
    }

    float acc[8][8];
    #pragma unroll
    for (int i = 0; i < 8; i++)
        #pragma unroll
        for (int j = 0; j < 8; j++) acc[i][j] = 0.0f;

    const int lr = tid >> 2;          // 0..63 (row within half-tile)
    const int lc = (tid & 3) * 4;     // 0,4,8,12 (k-col of float4)
    const float* Ag = g_An + (size_t)(by * 128) * D_SZ;
    const float* Bg = g_Tn + (size_t)(bx * 128) * D_SZ;

    const int rb0 = (tid >> 4) * 8;
    const int cb0 = (tid & 15) * 8;

    for (int kt = 0; kt < D_SZ; kt += 16) {
        #pragma unroll
        for (int h = 0; h < 2; h++) {
            int r = lr + h * 64;
            float4 va = *(const float4*)(Ag + (size_t)r * D_SZ + kt + lc);
            As[lc + 0][r] = va.x; As[lc + 1][r] = va.y;
            As[lc + 2][r] = va.z; As[lc + 3][r] = va.w;
            float4 vb = *(const float4*)(Bg + (size_t)r * D_SZ + kt + lc);
            Bs[lc + 0][r] = vb.x; Bs[lc + 1][r] = vb.y;
            Bs[lc + 2][r] = vb.z; Bs[lc + 3][r] = vb.w;
        }
        __syncthreads();

        #pragma unroll
        for (int k = 0; k < 16; k++) {
            float4 a0 = *(const float4*)&As[k][rb0];
            float4 a1 = *(const float4*)&As[k][rb0 + 4];
            float4 b0 = *(const float4*)&Bs[k][cb0];
            float4 b1 = *(const float4*)&Bs[k][cb0 + 4];
            float ra[8] = {a0.x, a0.y, a0.z, a0.w, a1.x, a1.y, a1.z, a1.w};
            float rb[8] = {b0.x, b0.y, b0.z, b0.w, b1.x, b1.y, b1.z, b1.w};
            #pragma unroll
            for (int i = 0; i < 8; i++)
                #pragma unroll
                for (int j = 0; j < 8; j++)
                    acc[i][j] = fmaf(ra[i], rb[j], acc[i][j]);
        }
        __syncthreads();
    }

    // epilogue: diag + label-masked row/col max
    long long labR[8], labC[8];
    #pragma unroll
    for (int i = 0; i < 8; i++) {
        labR[i] = labels[by * 128 + rb0 + i];
        labC[i] = labels[bx * 128 + cb0 + i];
    }

    float rmax[8], cmax[8];
    #pragma unroll
    for (int i = 0; i < 8; i++) { rmax[i] = -3e38f; cmax[i] = -3e38f; }

    #pragma unroll
    for (int i = 0; i < 8; i++) {
        int gi = by * 128 + rb0 + i;
        #pragma unroll
        for (int j = 0; j < 8; j++) {
            int gj = bx * 128 + cb0 + j;
            float v = acc[i][j];
            if (gi == gj) g_diag[gi] = v;
            if (labR[i] != labC[j]) {
                rmax[i] = fmaxf(rmax[i], v);
                cmax[j] = fmaxf(cmax[j], v);
            }
        }
    }

    #pragma unroll
    for (int i = 0; i < 8; i++) {
        atomicMax(&smax_r[rb0 + i], fenc(rmax[i]));
        atomicMax(&smax_c[cb0 + i], fenc(cmax[i]));
    }
    __syncthreads();

    if (tid < 128) {
        atomicMax(&g_rowmax[by * 128 + tid], smax_r[tid]);
        atomicMax(&g_colmax[bx * 128 + tid], smax_c[tid]);
    }
}

// ---------------- per-row loss terms + deterministic reduction ----------------
__device__ __forceinline__ float loss_term(float d, float m) {
    bool valid = (d < 1.0f - 1e-5f) && (m + 0.2f > d);
    if (!valid) return 0.0f;
    float pl = fmaxf(0.2f * d * d - 0.7f * d + 0.5f, 0.0f);
    float nl = fmaxf(0.9f * m * m - 0.4f * m + 0.03f, 0.0f);
    return pl + nl;
}

__global__ void loss_kernel() {
    __shared__ float sdata[256];
    int i = blockIdx.x * 256 + threadIdx.x;
    float d  = g_diag[i];
    float mr = fdec(g_rowmax[i]);
    float mc = fdec(g_colmax[i]);
    float c  = loss_term(d, mr) + loss_term(d, mc);
    sdata[threadIdx.x] = c;
    __syncthreads();
    #pragma unroll
    for (int s = 128; s > 0; s >>= 1) {
        if (threadIdx.x < s) sdata[threadIdx.x] += sdata[threadIdx.x + s];
        __syncthreads();
    }
    if (threadIdx.x == 0) g_partial[blockIdx.x] = sdata[0];
}

__global__ void final_kernel(float* __restrict__ out) {
    float s = (threadIdx.x < 32) ? g_partial[threadIdx.x] : 0.0f;
    #pragma unroll
    for (int o = 16; o > 0; o >>= 1) s += __shfl_xor_sync(0xffffffffu, s, o);
    if (threadIdx.x == 0) out[0] = s / (float)B_SZ;
}

// ---------------- launch ----------------
extern "C" void kernel_launch(void* const* d_in, const int* in_sizes, int n_in,
                              void* d_out, int out_size) {
    const float*     A      = (const float*)d_in[0];
    const float*     T      = (const float*)d_in[1];
    const long long* labels = (const long long*)d_in[2];
    float*           out    = (float*)d_out;

    init_kernel<<<(B_SZ + 255) / 256, 256>>>();
    normalize_kernel<<<(2 * B_SZ) / 8, dim3(32, 8)>>>(A, T);
    gemm_max_kernel<<<dim3(B_SZ / 128, B_SZ / 128), 256>>>(labels);
    loss_kernel<<<B_SZ / 256, 256>>>();
    final_kernel<<<1, 32>>>(out);
}

// round 3
// speedup vs baseline: 5.8332x; 5.8332x over previous
#include <cuda_runtime.h>
#include <cuda_bf16.h>
#include <cstdint>

#define B_SZ 8192
#define D_SZ 256

// ---------------- device scratch ----------------
__device__ unsigned short g_Anb[B_SZ * D_SZ];   // normalized audio, bf16
__device__ unsigned short g_Tnb[B_SZ * D_SZ];   // normalized text, bf16
__device__ unsigned g_rowmax[B_SZ];
__device__ unsigned g_colmax[B_SZ];
__device__ float    g_diag[B_SZ];               // exact fp32 diag
__device__ float    g_partial[32];

// Order-preserving float<->uint encoding for atomicMax on floats.
__device__ __forceinline__ unsigned fenc(float f) {
    unsigned u = __float_as_uint(f);
    return (u & 0x80000000u) ? ~u : (u | 0x80000000u);
}
__device__ __forceinline__ float fdec(unsigned u) {
    return (u & 0x80000000u) ? __uint_as_float(u ^ 0x80000000u) : __uint_as_float(~u);
}

// ---------------- init ----------------
__global__ void init_kernel() {
    int i = blockIdx.x * 256 + threadIdx.x;
    if (i < B_SZ) {
        unsigned s = fenc(-3e38f);
        g_rowmax[i] = s;
        g_colmax[i] = s;
    }
}

// ---------------- normalize + bf16 convert (1 warp / row) ----------------
__global__ void normalize_kernel(const float* __restrict__ A,
                                 const float* __restrict__ T) {
    int row  = blockIdx.x * blockDim.y + threadIdx.y;   // 0 .. 2B-1
    int lane = threadIdx.x;
    const float* src;
    unsigned short* dst;
    if (row < B_SZ) { src = A + (size_t)row * D_SZ;          dst = g_Anb + (size_t)row * D_SZ; }
    else            { src = T + (size_t)(row - B_SZ) * D_SZ; dst = g_Tnb + (size_t)(row - B_SZ) * D_SZ; }

    float4 v0 = ((const float4*)src)[2 * lane];
    float4 v1 = ((const float4*)src)[2 * lane + 1];
    float ss = v0.x*v0.x + v0.y*v0.y + v0.z*v0.z + v0.w*v0.w
             + v1.x*v1.x + v1.y*v1.y + v1.z*v1.z + v1.w*v1.w;
    #pragma unroll
    for (int o = 16; o > 0; o >>= 1) ss += __shfl_xor_sync(0xffffffffu, ss, o);
    float inv = 1.0f / sqrtf(ss);

    __nv_bfloat162 b0 = __floats2bfloat162_rn(v0.x * inv, v0.y * inv);
    __nv_bfloat162 b1 = __floats2bfloat162_rn(v0.z * inv, v0.w * inv);
    __nv_bfloat162 b2 = __floats2bfloat162_rn(v1.x * inv, v1.y * inv);
    __nv_bfloat162 b3 = __floats2bfloat162_rn(v1.z * inv, v1.w * inv);
    uint4 o4;
    o4.x = *(unsigned*)&b0; o4.y = *(unsigned*)&b1;
    o4.z = *(unsigned*)&b2; o4.w = *(unsigned*)&b3;
    *(uint4*)(dst + lane * 8) = o4;
}

// ---------------- exact fp32 diag ----------------
__global__ void diag_kernel(const float* __restrict__ A,
                            const float* __restrict__ T) {
    int row  = blockIdx.x * blockDim.y + threadIdx.y;
    int lane = threadIdx.x;
    const float* a = A + (size_t)row * D_SZ;
    const float* t = T + (size_t)row * D_SZ;
    float4 a0 = ((const float4*)a)[2 * lane];
    float4 a1 = ((const float4*)a)[2 * lane + 1];
    float4 t0 = ((const float4*)t)[2 * lane];
    float4 t1 = ((const float4*)t)[2 * lane + 1];
    float sa = a0.x*a0.x + a0.y*a0.y + a0.z*a0.z + a0.w*a0.w
             + a1.x*a1.x + a1.y*a1.y + a1.z*a1.z + a1.w*a1.w;
    float st = t0.x*t0.x + t0.y*t0.y + t0.z*t0.z + t0.w*t0.w
             + t1.x*t1.x + t1.y*t1.y + t1.z*t1.z + t1.w*t1.w;
    float dt = a0.x*t0.x + a0.y*t0.y + a0.z*t0.z + a0.w*t0.w
             + a1.x*t1.x + a1.y*t1.y + a1.z*t1.z + a1.w*t1.w;
    #pragma unroll
    for (int o = 16; o > 0; o >>= 1) {
        sa += __shfl_xor_sync(0xffffffffu, sa, o);
        st += __shfl_xor_sync(0xffffffffu, st, o);
        dt += __shfl_xor_sync(0xffffffffu, dt, o);
    }
    if (lane == 0) g_diag[row] = dt / (sqrtf(sa) * sqrtf(st));
}

// ---------------- warp-MMA GEMM tile + masked row/col max ----------------
// BM=BN=128, BK=32 bf16, 256 threads (8 warps, 2x4 warp grid, 64x32 per warp).
// Swizzle: byte = row*64 + (((grp) ^ ((row>>1)&3))<<4), grp = 16B group in row.

__device__ __forceinline__ void cp_async16(uint32_t saddr, const void* gaddr) {
    asm volatile("cp.async.cg.shared.global [%0], [%1], 16;" :: "r"(saddr), "l"(gaddr));
}
__device__ __forceinline__ void ldm_x4(uint32_t (&r)[4], uint32_t addr) {
    asm volatile("ldmatrix.sync.aligned.m8n8.x4.shared.b16 {%0,%1,%2,%3}, [%4];"
                 : "=r"(r[0]), "=r"(r[1]), "=r"(r[2]), "=r"(r[3]) : "r"(addr));
}
__device__ __forceinline__ void mma_bf16(float (&c)[4], const uint32_t (&a)[4],
                                         uint32_t b0, uint32_t b1) {
    asm volatile("mma.sync.aligned.m16n8k16.row.col.f32.bf16.bf16.f32 "
                 "{%0,%1,%2,%3}, {%4,%5,%6,%7}, {%8,%9}, {%0,%1,%2,%3};"
                 : "+f"(c[0]), "+f"(c[1]), "+f"(c[2]), "+f"(c[3])
                 : "r"(a[0]), "r"(a[1]), "r"(a[2]), "r"(a[3]), "r"(b0), "r"(b1));
}

__global__ void __launch_bounds__(256, 2)
gemm_max_kernel(const long long* __restrict__ labels) {
    __shared__ __align__(128) char smA[2][8192];
    __shared__ __align__(128) char smB[2][8192];
    __shared__ long long sLr[128];
    __shared__ long long sLc[128];
    __shared__ unsigned  s_rmax[128];
    __shared__ unsigned  s_cmax[128];

    const int tid  = threadIdx.x;
    const int w    = tid >> 5;
    const int lane = tid & 31;
    const int wm   = w >> 2;        // 0..1
    const int wn   = w & 3;         // 0..3
    const int bx   = blockIdx.x;    // N tile (text)
    const int by   = blockIdx.y;    // M tile (audio)

    if (tid < 128) {
        unsigned s = fenc(-3e38f);
        s_rmax[tid] = s;
        s_cmax[tid] = s;
        sLr[tid] = labels[by * 128 + tid];
        sLc[tid] = labels[bx * 128 + tid];
    }

    float acc[4][4][4];
    #pragma unroll
    for (int i = 0; i < 4; i++)
        #pragma unroll
        for (int j = 0; j < 4; j++)
            #pragma unroll
            for (int e = 0; e < 4; e++) acc[i][j][e] = 0.0f;

    const unsigned short* Ag = g_Anb + (size_t)(by * 128) * D_SZ;
    const unsigned short* Bg = g_Tnb + (size_t)(bx * 128) * D_SZ;

    // per-thread load coords: two 16B chunks per tile per thread
    // chunk c: row = c>>2 (0..127), grp = c&3 (16B group within 64B k-slab)
    auto sm_off = [](int row, int grp) -> int {
        return row * 64 + (((grp) ^ ((row >> 1) & 3)) << 4);
    };

    // prologue: stage 0
    {
        #pragma unroll
        for (int p = 0; p < 2; ++p) {
            int c = p * 256 + tid;
            int row = c >> 2, grp = c & 3;
            int so = sm_off(row, grp);
            cp_async16((uint32_t)__cvta_generic_to_shared(&smA[0][so]),
                       Ag + (size_t)row * D_SZ + grp * 8);
            cp_async16((uint32_t)__cvta_generic_to_shared(&smB[0][so]),
                       Bg + (size_t)row * D_SZ + grp * 8);
        }
        asm volatile("cp.async.commit_group;");
    }

    const int lrow = lane & 15;     // ldmatrix row-within-16
    const int lhi  = lane >> 4;     // 0: k-lo 16B, 1: k-hi 16B

    #pragma unroll
    for (int kt = 0; kt < 8; ++kt) {
        if (kt < 7) {
            int st = (kt + 1) & 1;
            int kofs = (kt + 1) * 32;
            #pragma unroll
            for (int p = 0; p < 2; ++p) {
                int c = p * 256 + tid;
                int row = c >> 2, grp = c & 3;
                int so = sm_off(row, grp);
                cp_async16((uint32_t)__cvta_generic_to_shared(&smA[st][so]),
                           Ag + (size_t)row * D_SZ + kofs + grp * 8);
                cp_async16((uint32_t)__cvta_generic_to_shared(&smB[st][so]),
                           Bg + (size_t)row * D_SZ + kofs + grp * 8);
            }
            asm volatile("cp.async.commit_group;");
            asm volatile("cp.async.wait_group 1;");
        } else {
            asm volatile("cp.async.wait_group 0;");
        }
        __syncthreads();

        const int s = kt & 1;
        #pragma unroll
        for (int ks = 0; ks < 2; ++ks) {
            uint32_t a[4][4];
            #pragma unroll
            for (int mf = 0; mf < 4; ++mf) {
                int row = wm * 64 + mf * 16 + lrow;
                int grp = ks * 2 + lhi;
                uint32_t ad = (uint32_t)__cvta_generic_to_shared(
                    &smA[s][row * 64 + ((grp ^ ((row >> 1) & 3)) << 4)]);
                ldm_x4(a[mf], ad);
            }
            uint32_t b[4][2];
            #pragma unroll
            for (int np = 0; np < 2; ++np) {
                int row = wn * 32 + np * 16 + lrow;
                int grp = ks * 2 + lhi;
                uint32_t bd = (uint32_t)__cvta_generic_to_shared(
                    &smB[s][row * 64 + ((grp ^ ((row >> 1) & 3)) << 4)]);
                uint32_t r[4];
                ldm_x4(r, bd);
                b[np * 2 + 0][0] = r[0];
                b[np * 2 + 1][0] = r[1];
                b[np * 2 + 0][1] = r[2];
                b[np * 2 + 1][1] = r[3];
            }
            #pragma unroll
            for (int mf = 0; mf < 4; ++mf)
                #pragma unroll
                for (int nf = 0; nf < 4; ++nf)
                    mma_bf16(acc[mf][nf], a[mf], b[nf][0], b[nf][1]);
        }
        __syncthreads();
    }

    // ---- epilogue: masked row/col max ----
    const int qr = lane >> 2;        // 0..7
    const int qc = (lane & 3) * 2;   // 0,2,4,6

    // row maxima
    #pragma unroll
    for (int mf = 0; mf < 4; ++mf) {
        #pragma unroll
        for (int h = 0; h < 2; ++h) {
            int rloc = wm * 64 + mf * 16 + qr + h * 8;
            long long labR = sLr[rloc];
            float rm = -3e38f;
            #pragma unroll
            for (int nf = 0; nf < 4; ++nf) {
                int cl = wn * 32 + nf * 8 + qc;
                float v0 = acc[mf][nf][h * 2 + 0];
                float v1 = acc[mf][nf][h * 2 + 1];
                if (labR != sLc[cl])     rm = fmaxf(rm, v0);
                if (labR != sLc[cl + 1]) rm = fmaxf(rm, v1);
            }
            atomicMax(&s_rmax[rloc], fenc(rm));
        }
    }
    // col maxima
    #pragma unroll
    for (int nf = 0; nf < 4; ++nf) {
        int cl = wn * 32 + nf * 8 + qc;
        long long lc0 = sLc[cl], lc1 = sLc[cl + 1];
        float cm0 = -3e38f, cm1 = -3e38f;
        #pragma unroll
        for (int mf = 0; mf < 4; ++mf) {
            #pragma unroll
            for (int h = 0; h < 2; ++h) {
                int rloc = wm * 64 + mf * 16 + qr + h * 8;
                long long labR = sLr[rloc];
                float v0 = acc[mf][nf][h * 2 + 0];
                float v1 = acc[mf][nf][h * 2 + 1];
                if (labR != lc0) cm0 = fmaxf(cm0, v0);
                if (labR != lc1) cm1 = fmaxf(cm1, v1);
            }
        }
        atomicMax(&s_cmax[cl],     fenc(cm0));
        atomicMax(&s_cmax[cl + 1], fenc(cm1));
    }

    __syncthreads();
    if (tid < 128) {
        atomicMax(&g_rowmax[by * 128 + tid], s_rmax[tid]);
        atomicMax(&g_colmax[bx * 128 + tid], s_cmax[tid]);
    }
}

// ---------------- loss + reduction ----------------
__device__ __forceinline__ float loss_term(float d, float m) {
    bool valid = (d < 1.0f - 1e-5f) && (m + 0.2f > d);
    if (!valid) return 0.0f;
    float pl = fmaxf(0.2f * d * d - 0.7f * d + 0.5f, 0.0f);
    float nl = fmaxf(0.9f * m * m - 0.4f * m + 0.03f, 0.0f);
    return pl + nl;
}

__global__ void loss_kernel() {
    __shared__ float sdata[256];
    int i = blockIdx.x * 256 + threadIdx.x;
    float d  = g_diag[i];
    float mr = fdec(g_rowmax[i]);
    float mc = fdec(g_colmax[i]);
    float c  = loss_term(d, mr) + loss_term(d, mc);
    sdata[threadIdx.x] = c;
    __syncthreads();
    #pragma unroll
    for (int s = 128; s > 0; s >>= 1) {
        if (threadIdx.x < s) sdata[threadIdx.x] += sdata[threadIdx.x + s];
        __syncthreads();
    }
    if (threadIdx.x == 0) g_partial[blockIdx.x] = sdata[0];
}

__global__ void final_kernel(float* __restrict__ out) {
    float s = (threadIdx.x < 32) ? g_partial[threadIdx.x] : 0.0f;
    #pragma unroll
    for (int o = 16; o > 0; o >>= 1) s += __shfl_xor_sync(0xffffffffu, s, o);
    if (threadIdx.x == 0) out[0] = s / (float)B_SZ;
}

// ---------------- launch ----------------
extern "C" void kernel_launch(void* const* d_in, const int* in_sizes, int n_in,
                              void* d_out, int out_size) {
    const float*     A      = (const float*)d_in[0];
    const float*     T      = (const float*)d_in[1];
    const long long* labels = (const long long*)d_in[2];
    float*           out    = (float*)d_out;

    init_kernel<<<(B_SZ + 255) / 256, 256>>>();
    normalize_kernel<<<(2 * B_SZ) / 8, dim3(32, 8)>>>(A, T);
    diag_kernel<<<B_SZ / 8, dim3(32, 8)>>>(A, T);
    gemm_max_kernel<<<dim3(B_SZ / 128, B_SZ / 128), 256>>>(labels);
    loss_kernel<<<B_SZ / 256, 256>>>();
    final_kernel<<<1, 32>>>(out);
}